// round 1
// baseline (speedup 1.0000x reference)
#include <cuda_runtime.h>
#include <cstdint>
#include <math.h>

#define NPTS 8192
#define DIM  256
#define NCLS 10
#define KNN  3

// ---------------- device scratch (static: no allocations allowed) ----------------
__device__ float g_d2[(size_t)NPTS * NPTS];   // clamped squared distances, 256 MB
__device__ float g_sq[NPTS];                  // row squared norms
__device__ int   g_m[NPTS];                   // m_i counts

// ---------------- kernel 1: row squared norms ----------------
__global__ void sq_kernel(const float* __restrict__ X) {
    int row  = blockIdx.x * 8 + (threadIdx.x >> 5);
    int lane = threadIdx.x & 31;
    const float* xr = X + (size_t)row * DIM;
    float s = 0.f;
    #pragma unroll
    for (int c = lane; c < DIM; c += 32) {
        float v = xr[c];
        s = fmaf(v, v, s);
    }
    #pragma unroll
    for (int o = 16; o; o >>= 1) s += __shfl_xor_sync(0xffffffffu, s, o);
    if (lane == 0) g_sq[row] = s;
}

// ---------------- kernel 2: fp32 SGEMM -> clamped d2 ----------------
// C tile 128x128, K-tile 16, 256 threads, 8x8 per-thread microtile (4+4 split
// to keep smem reads float4 / low-conflict).
__global__ void __launch_bounds__(256) gemm_d2_kernel(const float* __restrict__ X) {
    __shared__ float As[16][128];
    __shared__ float Bs[16][128];

    const int bi = blockIdx.y, bj = blockIdx.x;
    const int tid = threadIdx.x;
    const int tx = tid & 15, ty = tid >> 4;
    const int row0 = bi * 128, col0 = bj * 128;

    float acc[8][8];
    #pragma unroll
    for (int m = 0; m < 8; m++)
        #pragma unroll
        for (int n = 0; n < 8; n++) acc[m][n] = 0.f;

    // each thread loads 2 float4 per operand tile
    const int l0 = tid, l1 = tid + 256;

    for (int k0 = 0; k0 < DIM; k0 += 16) {
        {
            int r = l0 >> 2, kq = (l0 & 3) * 4;
            float4 v = *(const float4*)(X + (size_t)(row0 + r) * DIM + k0 + kq);
            As[kq + 0][r] = v.x; As[kq + 1][r] = v.y; As[kq + 2][r] = v.z; As[kq + 3][r] = v.w;
            v = *(const float4*)(X + (size_t)(col0 + r) * DIM + k0 + kq);
            Bs[kq + 0][r] = v.x; Bs[kq + 1][r] = v.y; Bs[kq + 2][r] = v.z; Bs[kq + 3][r] = v.w;

            r = l1 >> 2; kq = (l1 & 3) * 4;
            v = *(const float4*)(X + (size_t)(row0 + r) * DIM + k0 + kq);
            As[kq + 0][r] = v.x; As[kq + 1][r] = v.y; As[kq + 2][r] = v.z; As[kq + 3][r] = v.w;
            v = *(const float4*)(X + (size_t)(col0 + r) * DIM + k0 + kq);
            Bs[kq + 0][r] = v.x; Bs[kq + 1][r] = v.y; Bs[kq + 2][r] = v.z; Bs[kq + 3][r] = v.w;
        }
        __syncthreads();

        #pragma unroll
        for (int kk = 0; kk < 16; kk++) {
            float4 a0 = *(const float4*)&As[kk][ty * 4];
            float4 a1 = *(const float4*)&As[kk][64 + ty * 4];
            float4 b0 = *(const float4*)&Bs[kk][tx * 4];
            float4 b1 = *(const float4*)&Bs[kk][64 + tx * 4];
            float a[8] = {a0.x, a0.y, a0.z, a0.w, a1.x, a1.y, a1.z, a1.w};
            float b[8] = {b0.x, b0.y, b0.z, b0.w, b1.x, b1.y, b1.z, b1.w};
            #pragma unroll
            for (int m = 0; m < 8; m++)
                #pragma unroll
                for (int n = 0; n < 8; n++)
                    acc[m][n] = fmaf(a[m], b[n], acc[m][n]);
        }
        __syncthreads();
    }

    // epilogue: d2 = sq_i + sq_j - 2*dot, clamped at 0
    int irow[8], jcol[8];
    float sqi[8], sqj[8];
    #pragma unroll
    for (int m = 0; m < 8; m++) {
        int ro = (m < 4) ? (ty * 4 + m) : (64 + ty * 4 + m - 4);
        irow[m] = row0 + ro;
        sqi[m] = g_sq[irow[m]];
    }
    #pragma unroll
    for (int n = 0; n < 8; n++) {
        int co = (n < 4) ? (tx * 4 + n) : (64 + tx * 4 + n - 4);
        jcol[n] = col0 + co;
        sqj[n] = g_sq[jcol[n]];
    }
    #pragma unroll
    for (int m = 0; m < 8; m++) {
        float* orow = g_d2 + (size_t)irow[m] * NPTS;
        float4 o;
        o.x = fmaxf((sqi[m] + sqj[0]) - 2.f * acc[m][0], 0.f);
        o.y = fmaxf((sqi[m] + sqj[1]) - 2.f * acc[m][1], 0.f);
        o.z = fmaxf((sqi[m] + sqj[2]) - 2.f * acc[m][2], 0.f);
        o.w = fmaxf((sqi[m] + sqj[3]) - 2.f * acc[m][3], 0.f);
        *(float4*)(orow + jcol[0]) = o;
        o.x = fmaxf((sqi[m] + sqj[4]) - 2.f * acc[m][4], 0.f);
        o.y = fmaxf((sqi[m] + sqj[5]) - 2.f * acc[m][5], 0.f);
        o.z = fmaxf((sqi[m] + sqj[6]) - 2.f * acc[m][6], 0.f);
        o.w = fmaxf((sqi[m] + sqj[7]) - 2.f * acc[m][7], 0.f);
        *(float4*)(orow + jcol[4]) = o;
    }
}

// ---------------- kernel 3: per-row anchor (4th smallest same-class) + count ----------------
__device__ __forceinline__ void merge_sorted4(float* a, const float* b) {
    float r0, r1, r2, r3;
    int i = 0, j = 0;
    r0 = (a[0] <= b[0]) ? a[i++] : b[j++];
    r1 = (a[i] <= b[j]) ? a[i++] : b[j++];
    r2 = (a[i] <= b[j]) ? a[i++] : b[j++];
    r3 = (a[i] <= b[j]) ? a[i++] : b[j++];
    a[0] = r0; a[1] = r1; a[2] = r2; a[3] = r3;
}

__global__ void __launch_bounds__(256) row_stats_kernel(const int* __restrict__ y) {
    __shared__ int   ys[NPTS];           // 32 KB
    __shared__ float s4[256][4];         // 4 KB
    __shared__ int   scnt[8];
    __shared__ float s_anchor;

    const int row = blockIdx.x;
    const int tid = threadIdx.x;

    for (int j = tid; j < NPTS; j += 256) ys[j] = y[j];
    __syncthreads();

    const int yr = ys[row];
    const float* drow = g_d2 + (size_t)row * NPTS;

    // pass 1: per-thread sorted 4 smallest among same-class columns
    float b0 = INFINITY, b1 = INFINITY, b2 = INFINITY, b3 = INFINITY;
    for (int j = tid; j < NPTS; j += 256) {
        float v = drow[j];
        if (ys[j] == yr && v < b3) {
            if (v < b2) {
                b3 = b2;
                if (v < b1) {
                    b2 = b1;
                    if (v < b0) { b1 = b0; b0 = v; } else b1 = v;
                } else b2 = v;
            } else b3 = v;
        }
    }
    s4[tid][0] = b0; s4[tid][1] = b1; s4[tid][2] = b2; s4[tid][3] = b3;
    __syncthreads();

    for (int off = 128; off; off >>= 1) {
        if (tid < off) merge_sorted4(s4[tid], s4[tid + off]);
        __syncthreads();
    }
    if (tid == 0) s_anchor = s4[0][3];
    __syncthreads();
    const float anc = s_anchor;

    // pass 2: count strictly-below (row now hot in L1/L2)
    int cnt = 0;
    for (int j = tid; j < NPTS; j += 256) cnt += (drow[j] < anc) ? 1 : 0;
    #pragma unroll
    for (int o = 16; o; o >>= 1) cnt += __shfl_xor_sync(0xffffffffu, cnt, o);
    if ((tid & 31) == 0) scnt[tid >> 5] = cnt;
    __syncthreads();
    if (tid == 0) {
        int tot = 0;
        #pragma unroll
        for (int w = 0; w < 8; w++) tot += scnt[w];
        g_m[row] = tot - 1;   // exclude self
    }
}

// ---------------- kernel 4: finalize ----------------
__device__ double digamma_d(double x) {
    double r = 0.0;
    while (x < 6.0) { r -= 1.0 / x; x += 1.0; }
    double f = 1.0 / (x * x);
    double ser = f * (1.0 / 12.0 - f * (1.0 / 120.0 - f * (1.0 / 252.0
               - f * (1.0 / 240.0 - f * (1.0 / 132.0)))));
    return r + log(x) - 0.5 / x - ser;
}

__global__ void finalize_kernel(const int* __restrict__ y, float* __restrict__ out) {
    __shared__ int    hist[NCLS];
    __shared__ double sd[256];
    const int tid = threadIdx.x;

    if (tid < NCLS) hist[tid] = 0;
    __syncthreads();
    for (int j = tid; j < NPTS; j += 256) atomicAdd(&hist[y[j]], 1);
    __syncthreads();

    double local = 0.0;
    for (int r = tid; r < NPTS; r += 256) {
        float mf  = (float)g_m[r];
        float arg = mf + 1e-7f;          // mirror the reference's fp32 add
        local += digamma_d((double)arg);
    }
    sd[tid] = local;
    __syncthreads();
    for (int off = 128; off; off >>= 1) {
        if (tid < off) sd[tid] += sd[tid + off];
        __syncthreads();
    }

    if (tid == 0) {
        double avg_m = sd[0] / (double)NPTS;
        double avg_Nx = 0.0;
        for (int c = 0; c < NCLS; c++) {
            double nx = (double)hist[c];
            avg_Nx += (nx / (double)NPTS) * digamma_d(nx);
        }
        double mi = (digamma_d((double)NPTS) - avg_Nx
                   + digamma_d((double)KNN) - avg_m) / log(2.0);
        if (mi < 0.0) mi = 0.0;
        out[0] = (float)mi;
    }
}

// ---------------- launch ----------------
extern "C" void kernel_launch(void* const* d_in, const int* in_sizes, int n_in,
                              void* d_out, int out_size) {
    const float* X = (const float*)d_in[0];
    const int*   y = (const int*)d_in[1];
    float* out = (float*)d_out;
    (void)in_sizes; (void)n_in; (void)out_size;

    sq_kernel<<<NPTS / 8, 256>>>(X);
    dim3 ggrid(NPTS / 128, NPTS / 128);
    gemm_d2_kernel<<<ggrid, 256>>>(X);
    row_stats_kernel<<<NPTS, 256>>>(y);
    finalize_kernel<<<1, 256>>>(y, out);
}

// round 3
// speedup vs baseline: 2.4263x; 2.4263x over previous
#include <cuda_runtime.h>
#include <cuda_bf16.h>
#include <cstdint>
#include <math.h>

#define NPTS 8192
#define DIM  256
#define NCLS 10
#define KNN  3
#define NT   64          // 8192/128 tiles per dim
#define NTRI (NT*(NT+1)/2)

// ---------------- device scratch ----------------
__device__ float g_d2[(size_t)NPTS * NPTS];          // clamped squared distances (256 MB)
__device__ float g_sq[NPTS];
__device__ int   g_m[NPTS];
__device__ double g_part[64];
__device__ __nv_bfloat16 g_Xhi[(size_t)NPTS * DIM];  // 4 MB
__device__ __nv_bfloat16 g_Xlo[(size_t)NPTS * DIM];  // 4 MB

// ---------------- helpers ----------------
__device__ __forceinline__ uint32_t smem_u32(const void* p) {
    uint32_t a;
    asm("{ .reg .u64 t; cvta.to.shared.u64 t, %1; cvt.u32.u64 %0, t; }" : "=r"(a) : "l"(p));
    return a;
}
__device__ __forceinline__ void cp16(uint32_t dst, const void* src) {
    asm volatile("cp.async.cg.shared.global [%0], [%1], 16;" :: "r"(dst), "l"(src));
}
#define CP_COMMIT() asm volatile("cp.async.commit_group;" ::: "memory")
#define CP_WAIT0()  asm volatile("cp.async.wait_group 0;" ::: "memory")

#define MMA16816(d, a, b) \
  asm volatile("mma.sync.aligned.m16n8k16.row.col.f32.bf16.bf16.f32 " \
      "{%0,%1,%2,%3}, {%4,%5,%6,%7}, {%8,%9}, {%0,%1,%2,%3};" \
      : "+f"(d[0]), "+f"(d[1]), "+f"(d[2]), "+f"(d[3]) \
      : "r"(a[0]), "r"(a[1]), "r"(a[2]), "r"(a[3]), "r"(b[0]), "r"(b[1]))

// ---------------- kernel 1: split X -> bf16 hi/lo + squared norms ----------------
__global__ void __launch_bounds__(256) prep_kernel(const float* __restrict__ X) {
    int row  = blockIdx.x * 8 + (threadIdx.x >> 5);
    int lane = threadIdx.x & 31;
    const float* xr = X + (size_t)row * DIM + lane * 8;
    float4 v0 = *(const float4*)xr;
    float4 v1 = *(const float4*)(xr + 4);
    float v[8] = {v0.x, v0.y, v0.z, v0.w, v1.x, v1.y, v1.z, v1.w};
    uint32_t ph[4], pl[4];
    float s = 0.f;
    #pragma unroll
    for (int q = 0; q < 4; q++) {
        float a = v[2 * q], b = v[2 * q + 1];
        __nv_bfloat16 ha = __float2bfloat16(a), hb = __float2bfloat16(b);
        __nv_bfloat16 la = __float2bfloat16(a - __bfloat162float(ha));
        __nv_bfloat16 lb = __float2bfloat16(b - __bfloat162float(hb));
        ph[q] = ((uint32_t)__bfloat16_as_ushort(hb) << 16) | __bfloat16_as_ushort(ha);
        pl[q] = ((uint32_t)__bfloat16_as_ushort(lb) << 16) | __bfloat16_as_ushort(la);
        s = fmaf(a, a, fmaf(b, b, s));
    }
    size_t off = (size_t)row * DIM + lane * 8;
    *(uint4*)(g_Xhi + off) = make_uint4(ph[0], ph[1], ph[2], ph[3]);
    *(uint4*)(g_Xlo + off) = make_uint4(pl[0], pl[1], pl[2], pl[3]);
    #pragma unroll
    for (int o = 16; o; o >>= 1) s += __shfl_xor_sync(0xffffffffu, s, o);
    if (lane == 0) g_sq[row] = s;
}

// ---------------- kernel 2: mma.sync split-bf16 symmetric GEMM -> clamped d2 ----------
// Upper-triangular 128x128 tiles. K-chunk 32, cp.async double buffer.
// Operand tiles in smem: pitch 80 B (32 bf16 + 8 pad) -> conflict-free frag loads.
// Per-stage: 4 tiles (Ahi, Alo, Bhi, Blo) x 10240 B = 40960 B; 2 stages = 81920 B.
// Epilogue reuses the operand smem as a 128 x 132-float transpose buffer (67.6 KB).
#define TPITCH   80
#define TILE_SB  (128 * TPITCH)
#define STAGE_SB (4 * TILE_SB)
#define GSMEM    (2 * STAGE_SB)

__global__ void __launch_bounds__(256) gemm_kernel() {
    extern __shared__ char smem[];
    const int tid = threadIdx.x, wid = tid >> 5, lane = tid & 31;
    const int warp_m = wid >> 2, warp_n = wid & 3;

    // decode triangular tile index
    int idx = blockIdx.x;
    int bi = (int)((2 * NT + 1 - sqrtf((float)((2 * NT + 1) * (2 * NT + 1) - 8 * idx))) * 0.5f);
    while ((bi + 1) * NT - ((bi + 1) * bi) / 2 <= idx) bi++;
    while (bi * NT - (bi * (bi - 1)) / 2 > idx) bi--;
    int bj = bi + (idx - (bi * NT - (bi * (bi - 1)) / 2));
    const int row0 = bi * 128, col0 = bj * 128;

    const __nv_bfloat16* srcs[4] = {
        g_Xhi + (size_t)row0 * DIM, g_Xlo + (size_t)row0 * DIM,
        g_Xhi + (size_t)col0 * DIM, g_Xlo + (size_t)col0 * DIM };

    const uint32_t sb = smem_u32(smem);

    auto load_stage = [&](int stage, int kc) {
        uint32_t base = sb + stage * STAGE_SB;
        #pragma unroll
        for (int i = 0; i < 8; i++) {
            int gid = tid + i * 256;
            int tile = gid >> 9, rem = gid & 511;
            int r = rem >> 2, c = rem & 3;
            cp16(base + tile * TILE_SB + r * TPITCH + c * 16,
                 srcs[tile] + (size_t)r * DIM + kc * 32 + c * 8);
        }
        CP_COMMIT();
    };

    float acc[4][4][4];
    #pragma unroll
    for (int mt = 0; mt < 4; mt++)
        #pragma unroll
        for (int nt = 0; nt < 4; nt++)
            #pragma unroll
            for (int e = 0; e < 4; e++) acc[mt][nt][e] = 0.f;

    load_stage(0, 0);
    CP_WAIT0(); __syncthreads();

    const int frag_r = lane >> 2;          // 0..7
    const int frag_k = lane & 3;           // word offset within k16

    #pragma unroll 1
    for (int kc = 0; kc < 8; kc++) {
        if (kc < 7) load_stage((kc + 1) & 1, kc + 1);

        const char* st = smem + (kc & 1) * STAGE_SB;
        #pragma unroll
        for (int ks = 0; ks < 2; ks++) {
            uint32_t ah[4][4], al[4][4], bh[4][2], bl[4][2];
            #pragma unroll
            for (int mt = 0; mt < 4; mt++) {
                int r = warp_m * 64 + mt * 16 + frag_r;
                const char* pa = st + r * TPITCH + ks * 32 + frag_k * 4;
                ah[mt][0] = *(const uint32_t*)(pa);
                ah[mt][1] = *(const uint32_t*)(pa + 8 * TPITCH);
                ah[mt][2] = *(const uint32_t*)(pa + 16);
                ah[mt][3] = *(const uint32_t*)(pa + 8 * TPITCH + 16);
                const char* pl = pa + TILE_SB;
                al[mt][0] = *(const uint32_t*)(pl);
                al[mt][1] = *(const uint32_t*)(pl + 8 * TPITCH);
                al[mt][2] = *(const uint32_t*)(pl + 16);
                al[mt][3] = *(const uint32_t*)(pl + 8 * TPITCH + 16);
            }
            #pragma unroll
            for (int nt = 0; nt < 4; nt++) {
                int n = warp_n * 32 + nt * 8 + frag_r;
                const char* pb = st + 2 * TILE_SB + n * TPITCH + ks * 32 + frag_k * 4;
                bh[nt][0] = *(const uint32_t*)(pb);
                bh[nt][1] = *(const uint32_t*)(pb + 16);
                bl[nt][0] = *(const uint32_t*)(pb + TILE_SB);
                bl[nt][1] = *(const uint32_t*)(pb + TILE_SB + 16);
            }
            #pragma unroll
            for (int mt = 0; mt < 4; mt++)
                #pragma unroll
                for (int nt = 0; nt < 4; nt++) {
                    MMA16816(acc[mt][nt], ah[mt], bh[nt]);
                    MMA16816(acc[mt][nt], ah[mt], bl[nt]);
                    MMA16816(acc[mt][nt], al[mt], bh[nt]);
                }
        }
        if (kc < 7) { CP_WAIT0(); __syncthreads(); }
    }
    __syncthreads();   // all warps done reading operand smem

    // gather sq values (L1/L2 hot)
    float sqi[8], sqj[8];
    #pragma unroll
    for (int mt = 0; mt < 4; mt++) {
        sqi[2 * mt]     = g_sq[row0 + warp_m * 64 + mt * 16 + frag_r];
        sqi[2 * mt + 1] = g_sq[row0 + warp_m * 64 + mt * 16 + frag_r + 8];
    }
    #pragma unroll
    for (int nt = 0; nt < 4; nt++) {
        sqj[2 * nt]     = g_sq[col0 + warp_n * 32 + nt * 8 + 2 * frag_k];
        sqj[2 * nt + 1] = g_sq[col0 + warp_n * 32 + nt * 8 + 2 * frag_k + 1];
    }

    // stage d2 tile in smem (pitch 132 floats)
    float* buf = (float*)smem;
    #pragma unroll
    for (int mt = 0; mt < 4; mt++) {
        int r0 = warp_m * 64 + mt * 16 + frag_r;
        #pragma unroll
        for (int nt = 0; nt < 4; nt++) {
            int c0 = warp_n * 32 + nt * 8 + 2 * frag_k;
            buf[r0 * 132 + c0]           = fmaxf(fmaf(-2.f, acc[mt][nt][0], sqi[2*mt]   + sqj[2*nt]),   0.f);
            buf[r0 * 132 + c0 + 1]       = fmaxf(fmaf(-2.f, acc[mt][nt][1], sqi[2*mt]   + sqj[2*nt+1]), 0.f);
            buf[(r0 + 8) * 132 + c0]     = fmaxf(fmaf(-2.f, acc[mt][nt][2], sqi[2*mt+1] + sqj[2*nt]),   0.f);
            buf[(r0 + 8) * 132 + c0 + 1] = fmaxf(fmaf(-2.f, acc[mt][nt][3], sqi[2*mt+1] + sqj[2*nt+1]), 0.f);
        }
    }
    __syncthreads();

    // straight write: float4, 16 iters
    {
        int r = tid >> 1, cq = (tid & 1) * 16;          // 2 threads per row, 16 float4 each
        float* orow = g_d2 + (size_t)(row0 + r) * NPTS + col0;
        const float* brow = buf + r * 132;
        #pragma unroll
        for (int q = 0; q < 16; q++)
            *(float4*)(orow + (cq + q) * 4) = *(const float4*)(brow + (cq + q) * 4);
    }
    // transposed write: 32-bit coalesced (skip if diagonal: same data)
    if (bi != bj) {
        int rr = tid & 127, cb = tid >> 7;              // 2 cols per pass
        #pragma unroll
        for (int it = 0; it < 64; it++) {
            int c = cb + it * 2;
            g_d2[(size_t)(col0 + c) * NPTS + row0 + rr] = buf[rr * 132 + c];
        }
    }
}

// ---------------- kernel 3: per-row anchor + count ----------------
__device__ __forceinline__ void merge_sorted4(float* a, const float* b) {
    float r0, r1, r2, r3;
    int i = 0, j = 0;
    r0 = (a[0] <= b[0]) ? a[i++] : b[j++];
    r1 = (a[i] <= b[j]) ? a[i++] : b[j++];
    r2 = (a[i] <= b[j]) ? a[i++] : b[j++];
    r3 = (a[i] <= b[j]) ? a[i++] : b[j++];
    a[0] = r0; a[1] = r1; a[2] = r2; a[3] = r3;
}

__global__ void __launch_bounds__(256) row_stats_kernel(const int* __restrict__ y) {
    __shared__ int   ys[NPTS];
    __shared__ float s4[256][4];
    __shared__ int   scnt[8];
    __shared__ float s_anchor;

    const int row = blockIdx.x;
    const int tid = threadIdx.x;

    for (int j = tid; j < NPTS; j += 256) ys[j] = y[j];
    __syncthreads();

    const int yr = ys[row];
    const float* drow = g_d2 + (size_t)row * NPTS;

    float b0 = INFINITY, b1 = INFINITY, b2 = INFINITY, b3 = INFINITY;
    for (int j = tid; j < NPTS; j += 256) {
        float v = drow[j];
        if (ys[j] == yr && v < b3) {
            if (v < b2) {
                b3 = b2;
                if (v < b1) {
                    b2 = b1;
                    if (v < b0) { b1 = b0; b0 = v; } else b1 = v;
                } else b2 = v;
            } else b3 = v;
        }
    }
    s4[tid][0] = b0; s4[tid][1] = b1; s4[tid][2] = b2; s4[tid][3] = b3;
    __syncthreads();

    for (int off = 128; off; off >>= 1) {
        if (tid < off) merge_sorted4(s4[tid], s4[tid + off]);
        __syncthreads();
    }
    if (tid == 0) s_anchor = s4[0][3];
    __syncthreads();
    const float anc = s_anchor;

    int cnt = 0;
    for (int j = tid; j < NPTS; j += 256) cnt += (drow[j] < anc) ? 1 : 0;
    #pragma unroll
    for (int o = 16; o; o >>= 1) cnt += __shfl_xor_sync(0xffffffffu, cnt, o);
    if ((tid & 31) == 0) scnt[tid >> 5] = cnt;
    __syncthreads();
    if (tid == 0) {
        int tot = 0;
        #pragma unroll
        for (int w = 0; w < 8; w++) tot += scnt[w];
        g_m[row] = tot - 1;
    }
}

// ---------------- kernel 4: finalize ----------------
__device__ double digamma_d(double x) {
    double r = 0.0;
    while (x < 6.0) { r -= 1.0 / x; x += 1.0; }
    double f = 1.0 / (x * x);
    double ser = f * (1.0 / 12.0 - f * (1.0 / 120.0 - f * (1.0 / 252.0
               - f * (1.0 / 240.0 - f * (1.0 / 132.0)))));
    return r + log(x) - 0.5 / x - ser;
}

__global__ void fin_part_kernel() {
    __shared__ double sd[128];
    const int tid = threadIdx.x;
    int r = blockIdx.x * 128 + tid;
    float arg = (float)g_m[r] + 1e-7f;
    sd[tid] = digamma_d((double)arg);
    __syncthreads();
    for (int off = 64; off; off >>= 1) {
        if (tid < off) sd[tid] += sd[tid + off];
        __syncthreads();
    }
    if (tid == 0) g_part[blockIdx.x] = sd[0];
}

__global__ void fin2_kernel(const int* __restrict__ y, float* __restrict__ out) {
    __shared__ int hist[NCLS];
    const int tid = threadIdx.x;
    if (tid < NCLS) hist[tid] = 0;
    __syncthreads();
    for (int j = tid; j < NPTS; j += 256) atomicAdd(&hist[y[j]], 1);
    __syncthreads();
    if (tid == 0) {
        double s = 0.0;
        for (int b = 0; b < 64; b++) s += g_part[b];
        double avg_m = s / (double)NPTS;
        double avg_Nx = 0.0;
        for (int c = 0; c < NCLS; c++) {
            double nx = (double)hist[c];
            avg_Nx += (nx / (double)NPTS) * digamma_d(nx);
        }
        double mi = (digamma_d((double)NPTS) - avg_Nx
                   + digamma_d((double)KNN) - avg_m) / log(2.0);
        if (mi < 0.0) mi = 0.0;
        out[0] = (float)mi;
    }
}

// ---------------- launch ----------------
extern "C" void kernel_launch(void* const* d_in, const int* in_sizes, int n_in,
                              void* d_out, int out_size) {
    const float* X = (const float*)d_in[0];
    const int*   y = (const int*)d_in[1];
    float* out = (float*)d_out;
    (void)in_sizes; (void)n_in; (void)out_size;

    cudaFuncSetAttribute(gemm_kernel, cudaFuncAttributeMaxDynamicSharedMemorySize, GSMEM);

    prep_kernel<<<NPTS / 8, 256>>>(X);
    gemm_kernel<<<NTRI, 256, GSMEM>>>();
    row_stats_kernel<<<NPTS, 256>>>(y);
    fin_part_kernel<<<64, 128>>>();
    fin2_kernel<<<1, 256>>>(y, out);
}